// round 7
// baseline (speedup 1.0000x reference)
#include <cuda_runtime.h>
#include <cstdint>
#include <cstddef>

// Problem constants (fixed by the dataset)
#define NBUG   200000
#define NUSER  100000
#define INDIM  256
#define HIDC   128
#define OUTC   64
#define NCLS_C 128
#define EMAX   2000000

// ----------------------------------------------------------------------------
// Scratch (static __device__ globals — the allowed workaround for no-alloc rule)
// ----------------------------------------------------------------------------
__device__ float g_hb1[(size_t)NBUG * HIDC];    // layer-1 bug projection
__device__ float g_hu1[(size_t)NUSER * HIDC];   // layer-1 user projection
__device__ float g_ob [(size_t)NBUG * HIDC];    // relu(z_bug1)  (= elu'd, since elu∘relu = relu)
__device__ float g_ou [(size_t)NUSER * HIDC];   // relu(z_user1)
__device__ float g_hb2[(size_t)NBUG * OUTC];    // layer-2 bug projection
__device__ float g_hu2[(size_t)NUSER * OUTC];   // layer-2 user projection
__device__ float g_zb2[(size_t)NBUG * OUTC];    // relu(z_bug2)

__device__ float g_s_bu_src[NBUG * 2];
__device__ float g_s_ub_dst[NBUG * 2];
__device__ float g_s_bu_dst[NUSER * 2];
__device__ float g_s_ub_src[NUSER * 2];
__device__ float g_s2_src[NUSER];
__device__ float g_s2_dst[NBUG];

__device__ int g_col_u[EMAX];     // CSR (dst = user): src indices in segment order
__device__ int g_col_b[EMAX];     // CSR (dst = bug)
__device__ int g_deg_u[NUSER];
__device__ int g_deg_b[NBUG];
__device__ int g_rowptr_u[NUSER + 1];
__device__ int g_rowptr_b[NBUG + 1];
__device__ int g_cur_u[NUSER];
__device__ int g_cur_b[NBUG];
__device__ int g_bsum[1024];
__device__ int g_boff[1024];

// ----------------------------------------------------------------------------
// Tensor-core GEMM (tf32x3): C[M,N] = A[M,K] @ W[K,N] + bias
//   BM=64 BN=64 BK=32, 128 threads (4 warps, 2x2), warp tile 32x32.
//   m16n8k8 TF32 MMA with hi/lo split: D = Ah*Bh + Ah*Bl + Al*Bh  (~fp32 acc).
//   Requires K % 32 == 0, N % 64 == 0 (all shapes here satisfy this).
// ----------------------------------------------------------------------------
#define MMA_TF32(d, a, b)                                                     \
    asm volatile(                                                             \
        "mma.sync.aligned.m16n8k8.row.col.f32.tf32.tf32.f32 "                 \
        "{%0,%1,%2,%3}, {%4,%5,%6,%7}, {%8,%9}, {%0,%1,%2,%3};"               \
        : "+f"((d)[0]), "+f"((d)[1]), "+f"((d)[2]), "+f"((d)[3])              \
        : "r"((a)[0]), "r"((a)[1]), "r"((a)[2]), "r"((a)[3]),                 \
          "r"((b)[0]), "r"((b)[1]))

__device__ __forceinline__ void split_tf32(float x, uint32_t& hi, uint32_t& lo)
{
    uint32_t h;
    asm("cvt.rna.tf32.f32 %0, %1;" : "=r"(h) : "f"(x));
    float r = x - __uint_as_float(h);
    uint32_t l;
    asm("cvt.rna.tf32.f32 %0, %1;" : "=r"(l) : "f"(r));
    hi = h; lo = l;
}

// SMEM strides chosen for conflict-free fragment LDS:
//   A frag lanes: addr = (g)*SA + tig       -> SA%32=4  -> 32 distinct banks
//   B frag lanes: addr = (tig)*SB + g       -> SB%32=8  -> 32 distinct banks
#define SA 36
#define SB 72

__global__ __launch_bounds__(128)
void tf32_gemm_kernel(const float* __restrict__ A, const float* __restrict__ W,
                      const float* __restrict__ bias, float* __restrict__ C,
                      int M, int K, int N)
{
    __shared__ uint32_t Ah[64 * SA], Al[64 * SA];
    __shared__ uint32_t Bh[32 * SB], Bl[32 * SB];

    const int tid  = threadIdx.x;
    const int warp = tid >> 5;
    const int lane = tid & 31;
    const int wm = warp >> 1;          // 0..1
    const int wn = warp & 1;           // 0..1
    const int g   = lane >> 2;         // 0..7
    const int tig = lane & 3;          // 0..3
    const int m0 = blockIdx.x * 64;
    const int n0 = blockIdx.y * 64;

    float acc[2][4][4];
#pragma unroll
    for (int mt = 0; mt < 2; mt++)
#pragma unroll
        for (int nt = 0; nt < 4; nt++)
#pragma unroll
            for (int r = 0; r < 4; r++) acc[mt][nt][r] = 0.f;

    // staging indices (4 float4 per thread for each of A and B)
    const int a_row = tid >> 3;            // +32*i later? no: idx = tid + i*128
    (void)a_row;

    for (int k0 = 0; k0 < K; k0 += 32) {
        // ---- global loads ----
        float4 av[4];
        int arow[4], ac4[4];
#pragma unroll
        for (int i = 0; i < 4; i++) {
            int idx = tid + i * 128;       // 0..511
            int row = idx >> 3;            // 0..63
            int c4  = idx & 7;             // 0..7
            arow[i] = row; ac4[i] = c4;
            if (m0 + row < M)
                av[i] = *(const float4*)(A + (size_t)(m0 + row) * K + k0 + c4 * 4);
            else
                av[i] = make_float4(0.f, 0.f, 0.f, 0.f);
        }
        float4 bv[4];
        int bk[4], bc4[4];
#pragma unroll
        for (int i = 0; i < 4; i++) {
            int idx = tid + i * 128;
            int k   = idx >> 4;            // 0..31
            int c4  = idx & 15;            // 0..15
            bk[i] = k; bc4[i] = c4;
            bv[i] = *(const float4*)(W + (size_t)(k0 + k) * N + n0 + c4 * 4);
        }

        __syncthreads();   // previous iter's compute done with smem

        // ---- split + store to smem ----
#pragma unroll
        for (int i = 0; i < 4; i++) {
            uint32_t* ph = &Ah[arow[i] * SA + ac4[i] * 4];
            uint32_t* pl = &Al[arow[i] * SA + ac4[i] * 4];
            const float* v = &av[i].x;
#pragma unroll
            for (int j = 0; j < 4; j++) split_tf32(v[j], ph[j], pl[j]);
        }
#pragma unroll
        for (int i = 0; i < 4; i++) {
            uint32_t* ph = &Bh[bk[i] * SB + bc4[i] * 4];
            uint32_t* pl = &Bl[bk[i] * SB + bc4[i] * 4];
            const float* v = &bv[i].x;
#pragma unroll
            for (int j = 0; j < 4; j++) split_tf32(v[j], ph[j], pl[j]);
        }

        __syncthreads();

        // ---- compute: 4 k-steps of 8 ----
#pragma unroll
        for (int ks = 0; ks < 4; ks++) {
            const int kk = ks * 8;
            uint32_t ah[2][4], al[2][4];
#pragma unroll
            for (int mt = 0; mt < 2; mt++) {
                const int mr = wm * 32 + mt * 16;
                ah[mt][0] = Ah[(mr + g    ) * SA + kk + tig    ];
                ah[mt][1] = Ah[(mr + g + 8) * SA + kk + tig    ];
                ah[mt][2] = Ah[(mr + g    ) * SA + kk + tig + 4];
                ah[mt][3] = Ah[(mr + g + 8) * SA + kk + tig + 4];
                al[mt][0] = Al[(mr + g    ) * SA + kk + tig    ];
                al[mt][1] = Al[(mr + g + 8) * SA + kk + tig    ];
                al[mt][2] = Al[(mr + g    ) * SA + kk + tig + 4];
                al[mt][3] = Al[(mr + g + 8) * SA + kk + tig + 4];
            }
            uint32_t bh[4][2], bl[4][2];
#pragma unroll
            for (int nt = 0; nt < 4; nt++) {
                const int nc = wn * 32 + nt * 8;
                bh[nt][0] = Bh[(kk + tig    ) * SB + nc + g];
                bh[nt][1] = Bh[(kk + tig + 4) * SB + nc + g];
                bl[nt][0] = Bl[(kk + tig    ) * SB + nc + g];
                bl[nt][1] = Bl[(kk + tig + 4) * SB + nc + g];
            }
#pragma unroll
            for (int mt = 0; mt < 2; mt++)
#pragma unroll
                for (int nt = 0; nt < 4; nt++) {
                    MMA_TF32(acc[mt][nt], ah[mt], bh[nt]);   // hi*hi
                    MMA_TF32(acc[mt][nt], al[mt], bh[nt]);   // lo*hi
                    MMA_TF32(acc[mt][nt], ah[mt], bl[nt]);   // hi*lo
                }
        }
    }

    // ---- epilogue: add bias, store float2 per (tile,row) ----
#pragma unroll
    for (int mt = 0; mt < 2; mt++) {
        const int m_base = m0 + wm * 32 + mt * 16;
#pragma unroll
        for (int nt = 0; nt < 4; nt++) {
            const int col = n0 + wn * 32 + nt * 8 + 2 * tig;
            const float bx = bias[col], by = bias[col + 1];
            const int r0 = m_base + g;
            const int r1 = m_base + g + 8;
            if (r0 < M) {
                float2 o; o.x = acc[mt][nt][0] + bx; o.y = acc[mt][nt][1] + by;
                *(float2*)(C + (size_t)r0 * N + col) = o;
            }
            if (r1 < M) {
                float2 o; o.x = acc[mt][nt][2] + bx; o.y = acc[mt][nt][3] + by;
                *(float2*)(C + (size_t)r1 * N + col) = o;
            }
        }
    }
}

// ----------------------------------------------------------------------------
// Per-node attention scores: sA[i,h] = h[i,h,:]·attA[h,:], same for attB (opt)
// ----------------------------------------------------------------------------
template <int C, int H>
__global__ __launch_bounds__(256)
void scores_kernel(const float* __restrict__ h,
                   const float* __restrict__ attA, const float* __restrict__ attB,
                   float* __restrict__ sA, float* __restrict__ sB, int n)
{
    const int warp = (int)((blockIdx.x * (unsigned)blockDim.x + threadIdx.x) >> 5);
    const int lane = threadIdx.x & 31;
    if (warp >= n) return;
    constexpr int LANES = C / 4;
    constexpr int D4 = (C / H) / 4;   // lanes per head (16 here)
    const bool hasB = (sB != nullptr);

    float pa = 0.f, pb = 0.f;
    if (lane < LANES) {
        float4 hv = *(const float4*)(h + (size_t)warp * C + lane * 4);
        float4 aa = *(const float4*)(attA + lane * 4);
        pa = hv.x * aa.x + hv.y * aa.y + hv.z * aa.z + hv.w * aa.w;
        if (hasB) {
            float4 ab = *(const float4*)(attB + lane * 4);
            pb = hv.x * ab.x + hv.y * ab.y + hv.z * ab.z + hv.w * ab.w;
        }
    }
#pragma unroll
    for (int off = D4 / 2; off >= 1; off >>= 1) {
        pa += __shfl_down_sync(0xffffffffu, pa, off);
        pb += __shfl_down_sync(0xffffffffu, pb, off);
    }
    if (lane < LANES && (lane % D4) == 0) {
        int hh = lane / D4;
        sA[warp * H + hh] = pa;
        if (hasB) sB[warp * H + hh] = pb;
    }
}

// ----------------------------------------------------------------------------
// CSR build helpers
// ----------------------------------------------------------------------------
__global__ void hist_kernel(const int* __restrict__ dst, int E, int* __restrict__ deg)
{
    int e = blockIdx.x * blockDim.x + threadIdx.x;
    if (e < E) atomicAdd(&deg[dst[e]], 1);
}

__global__ void scatter_kernel(const int* __restrict__ src, const int* __restrict__ dst,
                               int* __restrict__ cur, int* __restrict__ col, int E)
{
    int e = blockIdx.x * blockDim.x + threadIdx.x;
    if (e < E) {
        int p = atomicAdd(&cur[dst[e]], 1);
        col[p] = src[e];
    }
}

__global__ __launch_bounds__(256)
void scan1_kernel(const int* __restrict__ in, int* __restrict__ out,
                  int* __restrict__ bsum, int n)
{
    __shared__ int sh[256];
    const int t = threadIdx.x;
    const int base = blockIdx.x * 1024 + t * 4;
    int v0 = (base + 0 < n) ? in[base + 0] : 0;
    int v1 = (base + 1 < n) ? in[base + 1] : 0;
    int v2 = (base + 2 < n) ? in[base + 2] : 0;
    int v3 = (base + 3 < n) ? in[base + 3] : 0;
    int tsum = v0 + v1 + v2 + v3;
    sh[t] = tsum;
    __syncthreads();
#pragma unroll
    for (int off = 1; off < 256; off <<= 1) {
        int x = (t >= off) ? sh[t - off] : 0;
        __syncthreads();
        sh[t] += x;
        __syncthreads();
    }
    if (bsum != nullptr && t == 255) bsum[blockIdx.x] = sh[255];
    int run = sh[t] - tsum;  // exclusive prefix
    if (base + 0 < n) out[base + 0] = run; run += v0;
    if (base + 1 < n) out[base + 1] = run; run += v1;
    if (base + 2 < n) out[base + 2] = run; run += v2;
    if (base + 3 < n) out[base + 3] = run;
}

__global__ __launch_bounds__(256)
void scan3_kernel(int* __restrict__ out, const int* __restrict__ boff, int n)
{
    const int base = blockIdx.x * 1024 + threadIdx.x * 4;
    int add = boff[blockIdx.x];
#pragma unroll
    for (int i = 0; i < 4; i++)
        if (base + i < n) out[base + i] += add;
}

__global__ void set_tail_kernel(int* p, int idx, int val) { p[idx] = val; }

// ----------------------------------------------------------------------------
// GAT segment-softmax aggregation, one warp per destination node.
// Phase 1: warp-online softmax stats; Phase 2: weighted float-vector gather.
// out = relu(segment_sum(alpha * h_src))
// ----------------------------------------------------------------------------
template <int C, int H>
__global__ __launch_bounds__(256)
void agg_kernel(const float* __restrict__ hsrc, const float* __restrict__ ssrc,
                const float* __restrict__ sdst, const int* __restrict__ rowptr,
                const int* __restrict__ col, float* __restrict__ out, int ndst)
{
    const int warp = (int)((blockIdx.x * (unsigned)blockDim.x + threadIdx.x) >> 5);
    const int lane = threadIdx.x & 31;
    if (warp >= ndst) return;
    constexpr int VEC = C / 32;   // 4 (C=128) or 2 (C=64)
    constexpr int D = C / H;

    const int start = rowptr[warp];
    const int end   = rowptr[warp + 1];

    float sd[H];
#pragma unroll
    for (int h = 0; h < H; h++) sd[h] = sdst[warp * H + h];

    // ---- phase 1: per-lane online (m,z), then warp merge ----
    float m[H], z[H];
#pragma unroll
    for (int h = 0; h < H; h++) { m[h] = -1e30f; z[h] = 0.f; }

    for (int e = start + lane; e < end; e += 32) {
        int s = col[e];
#pragma unroll
        for (int h = 0; h < H; h++) {
            float x = ssrc[s * H + h] + sd[h];
            float a = fmaxf(x, 0.2f * x);          // leaky_relu(0.2)
            if (a > m[h]) { z[h] = z[h] * __expf(m[h] - a) + 1.0f; m[h] = a; }
            else          { z[h] += __expf(a - m[h]); }
        }
    }
#pragma unroll
    for (int h = 0; h < H; h++) {
#pragma unroll
        for (int off = 16; off >= 1; off >>= 1) {
            float mo = __shfl_xor_sync(0xffffffffu, m[h], off);
            float zo = __shfl_xor_sync(0xffffffffu, z[h], off);
            float mn = fmaxf(m[h], mo);
            z[h] = z[h] * __expf(m[h] - mn) + zo * __expf(mo - mn);
            m[h] = mn;
        }
    }

    // ---- phase 2: weighted gather-accumulate ----
    const int hl = (lane * VEC) / D;
    const float mh  = m[hl];
    const float inv = 1.0f / fmaxf(z[hl], 1e-16f);
    const float sdh = sd[hl];

    float acc[VEC];
#pragma unroll
    for (int v = 0; v < VEC; v++) acc[v] = 0.f;

    for (int e = start; e < end; e++) {
        int s = col[e];   // same address across warp -> broadcast
        float x = ssrc[s * H + hl] + sdh;
        float a = fmaxf(x, 0.2f * x);
        float w = __expf(a - mh) * inv;
        const float* row = hsrc + (size_t)s * C + lane * VEC;
        if (VEC == 4) {
            float4 r = *(const float4*)row;
            acc[0] = fmaf(w, r.x, acc[0]);
            acc[1] = fmaf(w, r.y, acc[1]);
            acc[2] = fmaf(w, r.z, acc[2]);
            acc[3] = fmaf(w, r.w, acc[3]);
        } else {
            float2 r = *(const float2*)row;
            acc[0] = fmaf(w, r.x, acc[0]);
            acc[1] = fmaf(w, r.y, acc[1]);
        }
    }

    float* o = out + (size_t)warp * C + lane * VEC;
    if (VEC == 4) {
        float4 r;
        r.x = fmaxf(acc[0], 0.f); r.y = fmaxf(acc[1], 0.f);
        r.z = fmaxf(acc[2], 0.f); r.w = fmaxf(acc[3], 0.f);
        *(float4*)o = r;
    } else {
        float2 r;
        r.x = fmaxf(acc[0], 0.f); r.y = fmaxf(acc[1], 0.f);
        *(float2*)o = r;
    }
}

// ----------------------------------------------------------------------------
// Host launcher
// ----------------------------------------------------------------------------
static inline void* sym_addr(const void* sym)
{
    void* p = nullptr;
    cudaGetSymbolAddress(&p, sym);
    return p;
}

static void run_scan(int* deg, int* rowptr, int n, int total)
{
    int* bsum = (int*)sym_addr(g_bsum);
    int* boff = (int*)sym_addr(g_boff);
    int nb = (n + 1023) / 1024;
    scan1_kernel<<<nb, 256>>>(deg, rowptr, bsum, n);
    scan1_kernel<<<1, 256>>>(bsum, boff, nullptr, nb);
    scan3_kernel<<<nb, 256>>>(rowptr, boff, n);
    set_tail_kernel<<<1, 1>>>(rowptr, n, total);
}

extern "C" void kernel_launch(void* const* d_in, const int* in_sizes, int n_in,
                              void* d_out, int out_size)
{
    const float* xb      = (const float*)d_in[0];
    const float* xu      = (const float*)d_in[1];
    const int*   ebu_src = (const int*)d_in[2];
    const int*   ebu_dst = (const int*)d_in[3];
    const int*   eub_src = (const int*)d_in[4];
    const int*   eub_dst = (const int*)d_in[5];
    const float* w1_bug  = (const float*)d_in[6];
    const float* b1_bug  = (const float*)d_in[7];
    const float* w1_user = (const float*)d_in[8];
    const float* b1_user = (const float*)d_in[9];
    const float* a1_bu_s = (const float*)d_in[10];
    const float* a1_bu_d = (const float*)d_in[11];
    const float* a1_ub_s = (const float*)d_in[12];
    const float* a1_ub_d = (const float*)d_in[13];
    // d_in[14..16]: k1_w, k1_b, q1  — semantic attention over 1 relation == identity
    const float* w2_bug  = (const float*)d_in[17];
    const float* b2_bug  = (const float*)d_in[18];
    const float* w2_user = (const float*)d_in[19];
    const float* b2_user = (const float*)d_in[20];
    // d_in[21..22]: a2_bu_*  — layer-2 user branch is dead (output discarded)
    const float* a2_ub_s = (const float*)d_in[23];
    const float* a2_ub_d = (const float*)d_in[24];
    // d_in[25..27]: k2_w, k2_b, q2 — identity
    const float* wc      = (const float*)d_in[28];
    const float* bc      = (const float*)d_in[29];

    const int E = in_sizes[2];

    float* hb1 = (float*)sym_addr(g_hb1);
    float* hu1 = (float*)sym_addr(g_hu1);
    float* ob  = (float*)sym_addr(g_ob);
    float* ou  = (float*)sym_addr(g_ou);
    float* hb2 = (float*)sym_addr(g_hb2);
    float* hu2 = (float*)sym_addr(g_hu2);
    float* zb2 = (float*)sym_addr(g_zb2);
    float* s_bu_src = (float*)sym_addr(g_s_bu_src);
    float* s_ub_dst = (float*)sym_addr(g_s_ub_dst);
    float* s_bu_dst = (float*)sym_addr(g_s_bu_dst);
    float* s_ub_src = (float*)sym_addr(g_s_ub_src);
    float* s2_src   = (float*)sym_addr(g_s2_src);
    float* s2_dst   = (float*)sym_addr(g_s2_dst);
    int* col_u = (int*)sym_addr(g_col_u);
    int* col_b = (int*)sym_addr(g_col_b);
    int* deg_u = (int*)sym_addr(g_deg_u);
    int* deg_b = (int*)sym_addr(g_deg_b);
    int* rp_u  = (int*)sym_addr(g_rowptr_u);
    int* rp_b  = (int*)sym_addr(g_rowptr_b);
    int* cur_u = (int*)sym_addr(g_cur_u);
    int* cur_b = (int*)sym_addr(g_cur_b);

    const int eg = (E + 255) / 256;

    // ---- CSR build (both directions; eub CSR reused by layer 2) ----
    cudaMemsetAsync(deg_u, 0, NUSER * sizeof(int), 0);
    cudaMemsetAsync(deg_b, 0, NBUG * sizeof(int), 0);
    hist_kernel<<<eg, 256>>>(ebu_dst, E, deg_u);
    hist_kernel<<<eg, 256>>>(eub_dst, E, deg_b);
    run_scan(deg_u, rp_u, NUSER, E);
    run_scan(deg_b, rp_b, NBUG, E);
    cudaMemcpyAsync(cur_u, rp_u, NUSER * sizeof(int), cudaMemcpyDeviceToDevice, 0);
    cudaMemcpyAsync(cur_b, rp_b, NBUG * sizeof(int), cudaMemcpyDeviceToDevice, 0);
    scatter_kernel<<<eg, 256>>>(ebu_src, ebu_dst, cur_u, col_u, E);
    scatter_kernel<<<eg, 256>>>(eub_src, eub_dst, cur_b, col_b, E);

    // ---- Layer 1 projections (tensor-core tf32x3 GEMM) ----
    {
        dim3 g((NBUG + 63) / 64, HIDC / 64);
        tf32_gemm_kernel<<<g, 128>>>(xb, w1_bug, b1_bug, hb1, NBUG, INDIM, HIDC);
    }
    {
        dim3 g((NUSER + 63) / 64, HIDC / 64);
        tf32_gemm_kernel<<<g, 128>>>(xu, w1_user, b1_user, hu1, NUSER, INDIM, HIDC);
    }

    // ---- Layer 1 node scores (2 heads) ----
    scores_kernel<HIDC, 2><<<(NBUG + 7) / 8, 256>>>(hb1, a1_bu_s, a1_ub_d,
                                                    s_bu_src, s_ub_dst, NBUG);
    scores_kernel<HIDC, 2><<<(NUSER + 7) / 8, 256>>>(hu1, a1_ub_s, a1_bu_d,
                                                     s_ub_src, s_bu_dst, NUSER);

    // ---- Layer 1 edge attention + aggregation (fused relu; elu is a no-op after relu) ----
    agg_kernel<HIDC, 2><<<(NUSER + 7) / 8, 256>>>(hb1, s_bu_src, s_bu_dst,
                                                  rp_u, col_u, ou, NUSER);
    agg_kernel<HIDC, 2><<<(NBUG + 7) / 8, 256>>>(hu1, s_ub_src, s_ub_dst,
                                                 rp_b, col_b, ob, NBUG);

    // ---- Layer 2 projections ----
    {
        dim3 g((NBUG + 63) / 64, OUTC / 64);
        tf32_gemm_kernel<<<g, 128>>>(ob, w2_bug, b2_bug, hb2, NBUG, HIDC, OUTC);
    }
    {
        dim3 g((NUSER + 63) / 64, OUTC / 64);
        tf32_gemm_kernel<<<g, 128>>>(ou, w2_user, b2_user, hu2, NUSER, HIDC, OUTC);
    }

    // ---- Layer 2 scores (1 head) + user->bug aggregation only ----
    scores_kernel<OUTC, 1><<<(NUSER + 7) / 8, 256>>>(hu2, a2_ub_s, nullptr,
                                                     s2_src, nullptr, NUSER);
    scores_kernel<OUTC, 1><<<(NBUG + 7) / 8, 256>>>(hb2, a2_ub_d, nullptr,
                                                    s2_dst, nullptr, NBUG);
    agg_kernel<OUTC, 1><<<(NBUG + 7) / 8, 256>>>(hu2, s2_src, s2_dst,
                                                 rp_b, col_b, zb2, NBUG);

    // ---- Classifier ----
    {
        dim3 g((NBUG + 63) / 64, NCLS_C / 64);
        tf32_gemm_kernel<<<g, 128>>>(zb2, wc, bc, (float*)d_out, NBUG, OUTC, NCLS_C);
    }
}